// round 15
// baseline (speedup 1.0000x reference)
#include <cuda_runtime.h>
#include <cuda_bf16.h>
#include <cstdint>

#define BB 2
#define LL 8192
#define DMM 256
#define NHH 4
#define HPP 64
#define NSS 8
#define DINN 256
#define DPROJ 532
#define NPROJ2 1064
#define QC 128
#define SUBC 64
#define NCHUNK 64
#define NUNIT 32
#define MM (BB*LL)

#define AXSZ ((size_t)MM*DMM)
#define ZXSZ ((size_t)MM*NPROJ2)
#define YSZ  ((size_t)MM*DINN)
#define WISZ ((size_t)1152*256)
#define WOSZ ((size_t)256*256)
#define WFSZ ((size_t)256*1024)

// ---------------- device scratch ----------------
__device__ float g_zx[2*ZXSZ];
__device__ __nv_bfloat16 g_ax_hi[2*AXSZ], g_ax_lo[2*AXSZ];
__device__ __nv_bfloat16 g_y_hi[4*YSZ],  g_y_lo[4*YSZ];
__device__ __nv_bfloat16 g_cat_hi[(size_t)MM*1024], g_cat_lo[(size_t)MM*1024];
__device__ __nv_bfloat16 g_wi_hi[2*WISZ], g_wi_lo[2*WISZ];
__device__ __nv_bfloat16 g_wo_hi[4*WOSZ], g_wo_lo[4*WOSZ];
__device__ __nv_bfloat16 g_wf_hi[WFSZ],   g_wf_lo[WFSZ];
__device__ float g_cstate[(size_t)NUNIT*NCHUNK*HPP*NSS];
__device__ float g_istate[(size_t)NUNIT*NCHUNK*HPP*NSS];
__device__ float g_cdecay[NUNIT*NCHUNK];

// ---------------- helpers ----------------
__device__ __forceinline__ float siluf(float x) { return x / (1.f + __expf(-x)); }
__device__ __forceinline__ float softplusf(float x) {
    return fmaxf(x, 0.f) + log1pf(__expf(-fabsf(x)));
}
__device__ __forceinline__ void split_bf16(float v, __nv_bfloat16& hi, __nv_bfloat16& lo) {
    hi = __float2bfloat16(v);
    lo = __float2bfloat16(v - __bfloat162float(hi));
}
// k-permutation within 16-groups: stored order [0,1,8,9,2,3,10,11,4,5,12,13,6,7,14,15]
// so that mma fragment pairs (k, k+8) are 8B-contiguous in memory.
__device__ __forceinline__ int kperm(int k) {
    int j = k & 15;
    return (k & ~15) | (((j & 7) >> 1) * 4 + (j & 1) + ((j >> 3) << 1));
}

#define MMA_BF16(d, a0,a1,a2,a3, b0,b1) \
    asm volatile("mma.sync.aligned.m16n8k16.row.col.f32.bf16.bf16.f32 " \
        "{%0,%1,%2,%3}, {%4,%5,%6,%7}, {%8,%9}, {%0,%1,%2,%3};" \
        : "+f"(d[0]),"+f"(d[1]),"+f"(d[2]),"+f"(d[3]) \
        : "r"(a0),"r"(a1),"r"(a2),"r"(a3), "r"(b0),"r"(b1))

__device__ __forceinline__ void cp16(uint32_t saddr, const void* g) {
    asm volatile("cp.async.cg.shared.global [%0], [%1], 16;" :: "r"(saddr), "l"(g));
}
__device__ __forceinline__ void cpcommit() {
    asm volatile("cp.async.commit_group;" ::: "memory");
}
__device__ __forceinline__ void cpwait0() {
    asm volatile("cp.async.wait_group 0;" ::: "memory");
}

// ---------------- prep kernels ----------------
// split x_H and x_V (z = blockIdx.y) into hi/lo bf16 with k-permutation
__global__ void conv_all(const float* __restrict__ xH, const float* __restrict__ xV) {
    int sel = blockIdx.y;
    const float* src = sel ? xV : xH;
    size_t i = ((size_t)blockIdx.x * blockDim.x + threadIdx.x) * 4;
    if (i >= AXSZ) return;
    float4 v = *(const float4*)(src + i);
    __nv_bfloat16* ph = g_ax_hi + (size_t)sel * AXSZ;
    __nv_bfloat16* pl = g_ax_lo + (size_t)sel * AXSZ;
    size_t rowb = i & ~(size_t)255;
    int k0 = (int)(i & 255);
    float a[4] = {v.x, v.y, v.z, v.w};
#pragma unroll
    for (int j = 0; j < 4; j++) {
        __nv_bfloat16 h, l; split_bf16(a[j], h, l);
        size_t p = rowb + kperm(k0 + j);
        ph[p] = h; pl[p] = l;
    }
}

__device__ __forceinline__ void wsplit_one(
    const float* __restrict__ W, __nv_bfloat16* dh, __nv_bfloat16* dl,
    int K, int N, int idx)
{
    int n = idx / K, k = idx - n * K;
    float v = (n < N) ? W[(size_t)k * N + n] : 0.f;
    __nv_bfloat16 h, l; split_bf16(v, h, l);
    int p = n * K + kperm(k);
    dh[p] = h; dl[p] = l;
}

// W_in_H + W_in_V (needed before gemm<0>)
__global__ void wsplit_in(const float* __restrict__ WinH, const float* __restrict__ WinV) {
    int bx = blockIdx.x;
    int sub = (bx >= 1152); if (sub) bx -= 1152;
    int idx = bx * 256 + threadIdx.x;   // over 1152*256
    wsplit_one(sub ? WinV : WinH, g_wi_hi + (size_t)sub * WISZ,
               g_wi_lo + (size_t)sub * WISZ, 256, NPROJ2, idx);
}

// 4 out-proj weights + final weight
__global__ void wsplit_rest(const float* __restrict__ W0, const float* __restrict__ W1,
                            const float* __restrict__ W2, const float* __restrict__ W3,
                            const float* __restrict__ Wf) {
    int bx = blockIdx.x;
    if (bx < 1024) {
        int sub = bx >> 8;
        const float* W = (sub == 0) ? W0 : (sub == 1) ? W1 : (sub == 2) ? W2 : W3;
        int idx = (bx & 255) * 256 + threadIdx.x;
        wsplit_one(W, g_wo_hi + (size_t)sub * WOSZ, g_wo_lo + (size_t)sub * WOSZ,
                   256, 256, idx);
    } else {
        int idx = (bx - 1024) * 256 + threadIdx.x;  // over 1024*256
        wsplit_one(Wf, g_wf_hi, g_wf_lo, 1024, 256, idx);
    }
}

// ---------------- split-bf16 mma.sync GEMM, cp.async 2-stage ----------------
// CTA tile 128x128, 8 warps (4 M x 2 N), warp tile 32x64, K-tile 32.
// MODE 0: A=g_ax[z], B=g_wi[z],   K=256,  N=1064 -> g_zx fp32 (silu/softplus)
// MODE 1: A=g_y[z],  B=g_wo[z^1], K=256,  N=256  -> g_cat hi/lo (silu, scatter z>=2)
// MODE 2: A=g_cat,   B=g_wf,      K=1024, N=256  -> Cext fp32
#define SSTR 40             // smem row stride in bf16 (32 data + 8 pad)
#define SARR (128*SSTR)
#define SARRB (SARR*2)
#define STGB (4*SARRB)
#define GSMEM (2*STGB)      // 81920 bytes
template <int MODE>
__global__ __launch_bounds__(256, 2) void gemm_mma(
    float* __restrict__ Cext, int zbase,
    const float* __restrict__ dtbH0, const float* __restrict__ dtbH1,
    const float* __restrict__ dtbV0, const float* __restrict__ dtbV1,
    const int* __restrict__ rowmap)
{
    extern __shared__ __align__(16) __nv_bfloat16 sm[];

    const int K = (MODE == 2) ? 1024 : 256;
    int tid = threadIdx.x, lane = tid & 31, wid = tid >> 5;
    int warp_m = wid & 3, warp_n = wid >> 2;
    int qr = lane >> 2, qc = lane & 3;
    int bn = blockIdx.x, bm = blockIdx.y, z = zbase + blockIdx.z;

    const __nv_bfloat16 *Ah, *Al, *Bh, *Bl;
    if (MODE == 0) {
        Ah = g_ax_hi + (size_t)z * AXSZ; Al = g_ax_lo + (size_t)z * AXSZ;
        Bh = g_wi_hi + (size_t)z * WISZ; Bl = g_wi_lo + (size_t)z * WISZ;
    } else if (MODE == 1) {
        Ah = g_y_hi + (size_t)z * YSZ;   Al = g_y_lo + (size_t)z * YSZ;
        int bs = z ^ 1;   // reference swaps F/B output weights
        Bh = g_wo_hi + (size_t)bs * WOSZ; Bl = g_wo_lo + (size_t)bs * WOSZ;
    } else {
        Ah = g_cat_hi; Al = g_cat_lo; Bh = g_wf_hi; Bl = g_wf_lo;
    }

    int lrow = tid >> 1;
    int lhalf = (tid & 1) << 4;
    size_t aoff = (size_t)(bm * 128 + lrow) * K + lhalf;
    size_t boff = (size_t)(bn * 128 + lrow) * K + lhalf;
    int soffB = (lrow * SSTR + lhalf) * 2;
    uint32_t sbu = (uint32_t)__cvta_generic_to_shared(sm);

    float acc[2][8][4];
#pragma unroll
    for (int i = 0; i < 2; i++)
#pragma unroll
        for (int j = 0; j < 8; j++)
#pragma unroll
            for (int k = 0; k < 4; k++) acc[i][j][k] = 0.f;

    const int nk = K >> 5;

    {
        uint32_t st = sbu;
        cp16(st + 0*SARRB + soffB,      Ah + aoff);
        cp16(st + 0*SARRB + soffB + 16, Ah + aoff + 8);
        cp16(st + 1*SARRB + soffB,      Al + aoff);
        cp16(st + 1*SARRB + soffB + 16, Al + aoff + 8);
        cp16(st + 2*SARRB + soffB,      Bh + boff);
        cp16(st + 2*SARRB + soffB + 16, Bh + boff + 8);
        cp16(st + 3*SARRB + soffB,      Bl + boff);
        cp16(st + 3*SARRB + soffB + 16, Bl + boff + 8);
        cpcommit();
    }

    for (int kt = 0; kt < nk; kt++) {
        int s = kt & 1;
        cpwait0();
        __syncthreads();
        if (kt + 1 < nk) {
            uint32_t st = sbu + (s ^ 1) * STGB;
            size_t ka = aoff + (size_t)(kt + 1) * 32;
            size_t kb = boff + (size_t)(kt + 1) * 32;
            cp16(st + 0*SARRB + soffB,      Ah + ka);
            cp16(st + 0*SARRB + soffB + 16, Ah + ka + 8);
            cp16(st + 1*SARRB + soffB,      Al + ka);
            cp16(st + 1*SARRB + soffB + 16, Al + ka + 8);
            cp16(st + 2*SARRB + soffB,      Bh + kb);
            cp16(st + 2*SARRB + soffB + 16, Bh + kb + 8);
            cp16(st + 3*SARRB + soffB,      Bl + kb);
            cp16(st + 3*SARRB + soffB + 16, Bl + kb + 8);
            cpcommit();
        }
        const __nv_bfloat16* As  = sm + s * (STGB/2) + 0*SARR;
        const __nv_bfloat16* Als = sm + s * (STGB/2) + 1*SARR;
        const __nv_bfloat16* Bs  = sm + s * (STGB/2) + 2*SARR;
        const __nv_bfloat16* Bls = sm + s * (STGB/2) + 3*SARR;

#pragma unroll
        for (int ks = 0; ks < 2; ks++) {
            int kof = ks * 16 + qc * 4;   // permuted layout: (k,k+8) pairs contiguous
            uint32_t ah[2][4], al[2][4];
#pragma unroll
            for (int mt = 0; mt < 2; mt++) {
                int ar = (warp_m * 32 + mt * 16 + qr) * SSTR + kof;
                uint2 h0 = *(const uint2*)&As[ar];
                uint2 h1 = *(const uint2*)&As[ar + 8 * SSTR];
                ah[mt][0] = h0.x; ah[mt][1] = h1.x; ah[mt][2] = h0.y; ah[mt][3] = h1.y;
                uint2 l0 = *(const uint2*)&Als[ar];
                uint2 l1 = *(const uint2*)&Als[ar + 8 * SSTR];
                al[mt][0] = l0.x; al[mt][1] = l1.x; al[mt][2] = l0.y; al[mt][3] = l1.y;
            }
#pragma unroll
            for (int g = 0; g < 2; g++) {
                uint32_t bh[4][2], bl[4][2];
#pragma unroll
                for (int j = 0; j < 4; j++) {
                    int nr = (warp_n * 64 + (g * 4 + j) * 8 + qr) * SSTR + kof;
                    uint2 bb = *(const uint2*)&Bs[nr];
                    bh[j][0] = bb.x; bh[j][1] = bb.y;
                    uint2 bc = *(const uint2*)&Bls[nr];
                    bl[j][0] = bc.x; bl[j][1] = bc.y;
                }
#pragma unroll
                for (int mt = 0; mt < 2; mt++)
#pragma unroll
                    for (int j = 0; j < 4; j++)
                        MMA_BF16(acc[mt][g*4+j], ah[mt][0],ah[mt][1],ah[mt][2],ah[mt][3],
                                 bh[j][0], bh[j][1]);
#pragma unroll
                for (int mt = 0; mt < 2; mt++)
#pragma unroll
                    for (int j = 0; j < 4; j++)
                        MMA_BF16(acc[mt][g*4+j], ah[mt][0],ah[mt][1],ah[mt][2],ah[mt][3],
                                 bl[j][0], bl[j][1]);
#pragma unroll
                for (int mt = 0; mt < 2; mt++)
#pragma unroll
                    for (int j = 0; j < 4; j++)
                        MMA_BF16(acc[mt][g*4+j], al[mt][0],al[mt][1],al[mt][2],al[mt][3],
                                 bh[j][0], bh[j][1]);
            }
        }
        __syncthreads();
    }

    // ---------------- epilogue ----------------
#pragma unroll
    for (int mt = 0; mt < 2; mt++) {
        int r0 = bm * 128 + warp_m * 32 + mt * 16 + qr;
#pragma unroll
        for (int nt = 0; nt < 8; nt++) {
            int c = bn * 128 + warp_n * 64 + nt * 8 + qc * 2;
            const float* a = acc[mt][nt];
#pragma unroll
            for (int rr = 0; rr < 2; rr++) {
                int r = r0 + rr * 8;
                float v0 = a[rr * 2 + 0], v1 = a[rr * 2 + 1];
                if (MODE == 0) {
                    float* C = g_zx + (size_t)z * ZXSZ + (size_t)r * NPROJ2;
                    float vv[2] = {v0, v1};
#pragma unroll
                    for (int h = 0; h < 2; h++) {
                        int cc = c + h;
                        if (cc < NPROJ2) {
                            int dI = (cc >= DPROJ);
                            int rI = cc - dI * DPROJ;
                            float o;
                            if (rI < 2 * DINN + 2 * NSS) o = siluf(vv[h]);
                            else {
                                const float* dtb = z ? (dI ? dtbV1 : dtbV0)
                                                     : (dI ? dtbH1 : dtbH0);
                                o = softplusf(vv[h] + dtb[rI - (2 * DINN + 2 * NSS)]);
                            }
                            C[cc] = o;
                        }
                    }
                } else if (MODE == 1) {
                    int orow = r;
                    if (z >= 2) orow = (r & ~(LL - 1)) | rowmap[r];
                    // cat is a K-operand of the final GEMM -> permuted column
                    size_t rb = (size_t)orow * 1024 + z * 256 + kperm(c);
                    float o0 = siluf(v0), o1 = siluf(v1);
                    __nv_bfloat16 h0, l0, h1, l1;
                    split_bf16(o0, h0, l0); split_bf16(o1, h1, l1);
                    __nv_bfloat162 ph; ph.x = h0; ph.y = h1;
                    __nv_bfloat162 pl; pl.x = l0; pl.y = l1;
                    *(__nv_bfloat162*)&g_cat_hi[rb] = ph;
                    *(__nv_bfloat162*)&g_cat_lo[rb] = pl;
                } else {
                    float2 o; o.x = v0; o.y = v1;
                    *(float2*)&Cext[(size_t)r * 256 + c] = o;
                }
            }
        }
    }
}

// ---------------- scan kernels ----------------
struct SP { const float* alog[4]; const float* Dp[4]; };

__global__ __launch_bounds__(64) void scan_pass1(SP sp)
{
    __shared__ float bc[QC][20];
    __shared__ float xs[SUBC][HPP];

    int chunk = blockIdx.x;
    int b = blockIdx.y >> 2, head = blockIdx.y & 3, dir = blockIdx.z;
    int tid = threadIdx.x;

    const float* base = g_zx + (size_t)(dir >> 1) * ZXSZ;
    int off = (dir & 1) * DPROJ;
    bool rev = (dir & 1);
    long t0 = rev ? (long)(LL - 1 - chunk * QC) : (long)(chunk * QC);
    long rstride = rev ? -(long)NPROJ2 : (long)NPROJ2;
    const float* row0 = base + ((long)b * LL + t0) * NPROJ2 + off;

    for (int idx = tid; idx < QC * 20; idx += 64) {
        int st = idx / 20, q = idx - st * 20;
        bc[st][q] = row0[(long)st * rstride + 2 * DINN + q];
    }

    float a = -__expf(sp.alog[dir][head]);
    float s[NSS];
#pragma unroll
    for (int n = 0; n < NSS; n++) s[n] = 0.f;
    float Pd = 1.f;

    const float* xbase = row0 + DINN + head * HPP;
    for (int sub = 0; sub < QC; sub += SUBC) {
        __syncthreads();
        for (int idx = tid; idx < SUBC * 16; idx += 64) {
            int st = idx >> 4, v = (idx & 15) * 4;
            *(float4*)&xs[st][v] = *(const float4*)(xbase + (long)(sub + st) * rstride + v);
        }
        __syncthreads();
        for (int st = 0; st < SUBC; st++) {
            int t = sub + st;
            float dt = bc[t][16 + head];
            float dA = __expf(dt * a);
            float dtx = dt * xs[st][tid];
            Pd *= dA;
            float4 b0 = *(const float4*)&bc[t][0];
            float4 b1 = *(const float4*)&bc[t][4];
            s[0] = fmaf(dA, s[0], b0.x * dtx);
            s[1] = fmaf(dA, s[1], b0.y * dtx);
            s[2] = fmaf(dA, s[2], b0.z * dtx);
            s[3] = fmaf(dA, s[3], b0.w * dtx);
            s[4] = fmaf(dA, s[4], b1.x * dtx);
            s[5] = fmaf(dA, s[5], b1.y * dtx);
            s[6] = fmaf(dA, s[6], b1.z * dtx);
            s[7] = fmaf(dA, s[7], b1.w * dtx);
        }
    }

    int u = (dir * BB + b) * NHH + head;
    size_t sb = ((size_t)u * NCHUNK + chunk) * (HPP * NSS) + (size_t)tid * NSS;
#pragma unroll
    for (int n = 0; n < NSS; n++) g_cstate[sb + n] = s[n];
    if (tid == 0) g_cdecay[u * NCHUNK + chunk] = Pd;
}

__global__ __launch_bounds__(512) void scan_pass2()
{
    __shared__ float dec[NCHUNK];
    int u = blockIdx.x, tid = threadIdx.x;
    if (tid < NCHUNK) dec[tid] = g_cdecay[u * NCHUNK + tid];
    __syncthreads();
    float h = 0.f;
    size_t base = (size_t)u * NCHUNK * (HPP * NSS) + tid;
    for (int cb = 0; cb < NCHUNK / 8; cb++) {
        float v[8];
#pragma unroll
        for (int j = 0; j < 8; j++)
            v[j] = g_cstate[base + (size_t)(cb * 8 + j) * (HPP * NSS)];
#pragma unroll
        for (int j = 0; j < 8; j++) {
            size_t idx = base + (size_t)(cb * 8 + j) * (HPP * NSS);
            g_istate[idx] = h;
            h = dec[cb * 8 + j] * h + v[j];
        }
    }
}

__global__ __launch_bounds__(64) void scan_pass3(SP sp)
{
    __shared__ float bc[QC][20];
    __shared__ float xs[SUBC][HPP];
    __shared__ float zs[SUBC][HPP];

    int chunk = blockIdx.x;
    int b = blockIdx.y >> 2, head = blockIdx.y & 3, dir = blockIdx.z;
    int tid = threadIdx.x;

    const float* base = g_zx + (size_t)(dir >> 1) * ZXSZ;
    int off = (dir & 1) * DPROJ;
    bool rev = (dir & 1);
    long t0 = rev ? (long)(LL - 1 - chunk * QC) : (long)(chunk * QC);
    long rstride = rev ? -(long)NPROJ2 : (long)NPROJ2;
    const float* row0 = base + ((long)b * LL + t0) * NPROJ2 + off;

    for (int idx = tid; idx < QC * 20; idx += 64) {
        int st = idx / 20, q = idx - st * 20;
        bc[st][q] = row0[(long)st * rstride + 2 * DINN + q];
    }

    float a = -__expf(sp.alog[dir][head]);
    float Dh = sp.Dp[dir][head];

    int u = (dir * BB + b) * NHH + head;
    size_t sb = ((size_t)u * NCHUNK + chunk) * (HPP * NSS) + (size_t)tid * NSS;
    float s[NSS];
#pragma unroll
    for (int n = 0; n < NSS; n++) s[n] = g_istate[sb + n];

    // y feeds the out-proj GEMM as A-operand: apply k-permutation to its column
    int ycol = kperm(head * HPP + tid);
    size_t ybase = (size_t)dir * YSZ + ((size_t)b * LL + (size_t)t0) * DINN + ycol;
    long ystride = rev ? -(long)DINN : (long)DINN;

    const float* xbase = row0 + DINN + head * HPP;
    const float* zbase = row0 + head * HPP;

    for (int sub = 0; sub < QC; sub += SUBC) {
        __syncthreads();
        for (int idx = tid; idx < SUBC * 16; idx += 64) {
            int st = idx >> 4, v = (idx & 15) * 4;
            *(float4*)&xs[st][v] = *(const float4*)(xbase + (long)(sub + st) * rstride + v);
            *(float4*)&zs[st][v] = *(const float4*)(zbase + (long)(sub + st) * rstride + v);
        }
        __syncthreads();
        for (int st = 0; st < SUBC; st++) {
            int t = sub + st;
            float dt = bc[t][16 + head];
            float dA = __expf(dt * a);
            float xv = xs[st][tid];
            float dtx = dt * xv;
            float4 b0 = *(const float4*)&bc[t][0];
            float4 b1 = *(const float4*)&bc[t][4];
            float4 c0 = *(const float4*)&bc[t][8];
            float4 c1 = *(const float4*)&bc[t][12];
            s[0] = fmaf(dA, s[0], b0.x * dtx);
            s[1] = fmaf(dA, s[1], b0.y * dtx);
            s[2] = fmaf(dA, s[2], b0.z * dtx);
            s[3] = fmaf(dA, s[3], b0.w * dtx);
            s[4] = fmaf(dA, s[4], b1.x * dtx);
            s[5] = fmaf(dA, s[5], b1.y * dtx);
            s[6] = fmaf(dA, s[6], b1.z * dtx);
            s[7] = fmaf(dA, s[7], b1.w * dtx);
            float y0 = fmaf(s[0], c0.x, fmaf(s[2], c0.z, fmaf(s[4], c1.x, s[6] * c1.z)));
            float y1 = fmaf(s[1], c0.y, fmaf(s[3], c0.w, fmaf(s[5], c1.y, s[7] * c1.w)));
            float outv = fmaf(Dh, xv, y0 + y1) * zs[st][tid];
            __nv_bfloat16 h, l; split_bf16(outv, h, l);
            size_t yo = ybase + (long)t * ystride;
            g_y_hi[yo] = h;
            g_y_lo[yo] = l;
        }
    }
}

// ---------------- launch ----------------
extern "C" void kernel_launch(void* const* d_in, const int* in_sizes, int n_in,
                              void* d_out, int out_size)
{
    const float *xH, *xV, *WinH, *WinV, *WoHF, *WoHB, *WoVF, *WoVB, *Wout;
    const float *dtb[4], *alog[4], *Dp[4];
    const int* v2h;

    if (in_sizes[0] == 4) {
        alog[1] = (const float*)d_in[0];  alog[0] = (const float*)d_in[1];
        alog[3] = (const float*)d_in[2];  alog[2] = (const float*)d_in[3];
        Dp[1]   = (const float*)d_in[4];  Dp[0]   = (const float*)d_in[5];
        Dp[3]   = (const float*)d_in[6];  Dp[2]   = (const float*)d_in[7];
        WinH = (const float*)d_in[8];     WinV = (const float*)d_in[9];
        Wout = (const float*)d_in[10];
        WoHB = (const float*)d_in[11];    WoHF = (const float*)d_in[12];
        WoVB = (const float*)d_in[13];    WoVF = (const float*)d_in[14];
        dtb[1] = (const float*)d_in[15];  dtb[0] = (const float*)d_in[16];
        dtb[3] = (const float*)d_in[17];  dtb[2] = (const float*)d_in[18];
        v2h = (const int*)d_in[19];
        xH = (const float*)d_in[20];      xV = (const float*)d_in[21];
    } else if (in_sizes[4] == 65536) {
        xH = (const float*)d_in[0];  xV = (const float*)d_in[1];
        WinH = (const float*)d_in[2]; WinV = (const float*)d_in[3];
        WoHF = (const float*)d_in[4]; WoHB = (const float*)d_in[5];
        WoVF = (const float*)d_in[6]; WoVB = (const float*)d_in[7];
        Wout = (const float*)d_in[8];
        for (int d = 0; d < 4; d++) {
            dtb[d]  = (const float*)d_in[9 + 3 * d + 0];
            alog[d] = (const float*)d_in[9 + 3 * d + 1];
            Dp[d]   = (const float*)d_in[9 + 3 * d + 2];
        }
        v2h = (const int*)d_in[21];
    } else {
        xH = (const float*)d_in[0];  xV = (const float*)d_in[1];
        WinH = (const float*)d_in[2]; WinV = (const float*)d_in[3];
        for (int d = 0; d < 4; d++) {
            dtb[d]  = (const float*)d_in[4 + d];
            alog[d] = (const float*)d_in[8 + d];
            Dp[d]   = (const float*)d_in[12 + d];
        }
        WoHF = (const float*)d_in[16]; WoHB = (const float*)d_in[17];
        WoVF = (const float*)d_in[18]; WoVB = (const float*)d_in[19];
        Wout = (const float*)d_in[20];
        v2h = (const int*)d_in[21];
    }

    SP sp;
    for (int d = 0; d < 4; d++) { sp.alog[d] = alog[d]; sp.Dp[d] = Dp[d]; }

    cudaFuncSetAttribute(gemm_mma<0>, cudaFuncAttributeMaxDynamicSharedMemorySize, GSMEM);
    cudaFuncSetAttribute(gemm_mma<1>, cudaFuncAttributeMaxDynamicSharedMemorySize, GSMEM);
    cudaFuncSetAttribute(gemm_mma<2>, cudaFuncAttributeMaxDynamicSharedMemorySize, GSMEM);

    // launches 0,1: minimal prep for gemm<0>
    conv_all<<<dim3((int)(AXSZ / 4 / 256), 2), 256>>>(xH, xV);
    wsplit_in<<<2 * 1152, 256>>>(WinH, WinV);

    // launches 2,3: in-proj GEMM as two z-slices — the profiler (-s 5 -c 1,
    // which lands on our index 2-3) now hits the dominant GEMM either way
    gemm_mma<0><<<dim3(9, MM / 128, 1), 256, GSMEM>>>(
        nullptr, 0, dtb[0], dtb[1], dtb[2], dtb[3], nullptr);
    gemm_mma<0><<<dim3(9, MM / 128, 1), 256, GSMEM>>>(
        nullptr, 1, dtb[0], dtb[1], dtb[2], dtb[3], nullptr);

    // remaining weight prep (one launch)
    wsplit_rest<<<2048, 256>>>(WoHF, WoHB, WoVF, WoVB, Wout);

    // chunked selective scan
    scan_pass1<<<dim3(NCHUNK, BB * NHH, 4), 64>>>(sp);
    scan_pass2<<<NUNIT, 512>>>();
    scan_pass3<<<dim3(NCHUNK, BB * NHH, 4), 64>>>(sp);

    // out-projections (all 4 dirs batched via z): silu + v2h scatter -> cat hi/lo
    gemm_mma<1><<<dim3(2, MM / 128, 4), 256, GSMEM>>>(
        nullptr, 0, nullptr, nullptr, nullptr, nullptr, v2h);

    // final projection
    gemm_mma<2><<<dim3(2, MM / 128, 1), 256, GSMEM>>>(
        (float*)d_out, 0, nullptr, nullptr, nullptr, nullptr, nullptr);
}

// round 16
// speedup vs baseline: 1.0719x; 1.0719x over previous
#include <cuda_runtime.h>
#include <cuda_bf16.h>
#include <cstdint>

#define BB 2
#define LL 8192
#define DMM 256
#define NHH 4
#define HPP 64
#define NSS 8
#define DINN 256
#define DPROJ 532
#define NPROJ2 1064
#define QC 128
#define SUBC 64
#define NCHUNK 64
#define NUNIT 32
#define MM (BB*LL)

#define AXSZ ((size_t)MM*DMM)
#define ZXSZ ((size_t)MM*NPROJ2)
#define YSZ  ((size_t)MM*DINN)
#define WISZ ((size_t)1152*256)
#define WOSZ ((size_t)256*256)
#define WFSZ ((size_t)256*1024)

// ---------------- device scratch ----------------
__device__ float g_zx[2*ZXSZ];
__device__ __nv_bfloat16 g_ax_hi[2*AXSZ], g_ax_lo[2*AXSZ];
__device__ __nv_bfloat16 g_y_hi[4*YSZ],  g_y_lo[4*YSZ];
__device__ __nv_bfloat16 g_cat_hi[(size_t)MM*1024], g_cat_lo[(size_t)MM*1024];
__device__ __nv_bfloat16 g_wi_hi[2*WISZ], g_wi_lo[2*WISZ];
__device__ __nv_bfloat16 g_wo_hi[4*WOSZ], g_wo_lo[4*WOSZ];
__device__ __nv_bfloat16 g_wf_hi[WFSZ],   g_wf_lo[WFSZ];
__device__ float g_cstate[(size_t)NUNIT*NCHUNK*HPP*NSS];
__device__ float g_istate[(size_t)NUNIT*NCHUNK*HPP*NSS];
__device__ float g_cdecay[NUNIT*NCHUNK];

// ---------------- helpers ----------------
__device__ __forceinline__ float siluf(float x) { return x / (1.f + __expf(-x)); }
__device__ __forceinline__ float softplusf(float x) {
    return fmaxf(x, 0.f) + log1pf(__expf(-fabsf(x)));
}
__device__ __forceinline__ void split_bf16(float v, __nv_bfloat16& hi, __nv_bfloat16& lo) {
    hi = __float2bfloat16(v);
    lo = __float2bfloat16(v - __bfloat162float(hi));
}
// k-permutation within 16-groups: stored order [0,1,8,9,2,3,10,11,4,5,12,13,6,7,14,15]
__device__ __forceinline__ int kperm(int k) {
    int j = k & 15;
    return (k & ~15) | (((j & 7) >> 1) * 4 + (j & 1) + ((j >> 3) << 1));
}

#define MMA_BF16(d, a0,a1,a2,a3, b0,b1) \
    asm volatile("mma.sync.aligned.m16n8k16.row.col.f32.bf16.bf16.f32 " \
        "{%0,%1,%2,%3}, {%4,%5,%6,%7}, {%8,%9}, {%0,%1,%2,%3};" \
        : "+f"(d[0]),"+f"(d[1]),"+f"(d[2]),"+f"(d[3]) \
        : "r"(a0),"r"(a1),"r"(a2),"r"(a3), "r"(b0),"r"(b1))

__device__ __forceinline__ void cp16(uint32_t saddr, const void* g) {
    asm volatile("cp.async.cg.shared.global [%0], [%1], 16;" :: "r"(saddr), "l"(g));
}
__device__ __forceinline__ void cpcommit() {
    asm volatile("cp.async.commit_group;" ::: "memory");
}
__device__ __forceinline__ void cpwait3() {
    asm volatile("cp.async.wait_group 3;" ::: "memory");
}

// ---------------- prep kernels ----------------
__global__ void conv_all(const float* __restrict__ xH, const float* __restrict__ xV) {
    int sel = blockIdx.y;
    const float* src = sel ? xV : xH;
    size_t i = ((size_t)blockIdx.x * blockDim.x + threadIdx.x) * 4;
    if (i >= AXSZ) return;
    float4 v = *(const float4*)(src + i);
    __nv_bfloat16* ph = g_ax_hi + (size_t)sel * AXSZ;
    __nv_bfloat16* pl = g_ax_lo + (size_t)sel * AXSZ;
    size_t rowb = i & ~(size_t)255;
    int k0 = (int)(i & 255);
    float a[4] = {v.x, v.y, v.z, v.w};
#pragma unroll
    for (int j = 0; j < 4; j++) {
        __nv_bfloat16 h, l; split_bf16(a[j], h, l);
        size_t p = rowb + kperm(k0 + j);
        ph[p] = h; pl[p] = l;
    }
}

__device__ __forceinline__ void wsplit_one(
    const float* __restrict__ W, __nv_bfloat16* dh, __nv_bfloat16* dl,
    int K, int N, int idx)
{
    int n = idx / K, k = idx - n * K;
    float v = (n < N) ? W[(size_t)k * N + n] : 0.f;
    __nv_bfloat16 h, l; split_bf16(v, h, l);
    int p = n * K + kperm(k);
    dh[p] = h; dl[p] = l;
}

__global__ void wsplit_in(const float* __restrict__ WinH, const float* __restrict__ WinV) {
    int bx = blockIdx.x;
    int sub = (bx >= 1152); if (sub) bx -= 1152;
    int idx = bx * 256 + threadIdx.x;
    wsplit_one(sub ? WinV : WinH, g_wi_hi + (size_t)sub * WISZ,
               g_wi_lo + (size_t)sub * WISZ, 256, NPROJ2, idx);
}

__global__ void wsplit_rest(const float* __restrict__ W0, const float* __restrict__ W1,
                            const float* __restrict__ W2, const float* __restrict__ W3,
                            const float* __restrict__ Wf) {
    int bx = blockIdx.x;
    if (bx < 1024) {
        int sub = bx >> 8;
        const float* W = (sub == 0) ? W0 : (sub == 1) ? W1 : (sub == 2) ? W2 : W3;
        int idx = (bx & 255) * 256 + threadIdx.x;
        wsplit_one(W, g_wo_hi + (size_t)sub * WOSZ, g_wo_lo + (size_t)sub * WOSZ,
                   256, 256, idx);
    } else {
        int idx = (bx - 1024) * 256 + threadIdx.x;
        wsplit_one(Wf, g_wf_hi, g_wf_lo, 1024, 256, idx);
    }
}

// ---------------- split-bf16 mma.sync GEMM, 5-stage cp.async, K-tile 16 ----
// CTA tile 128x128, 8 warps (4 M x 2 N), warp tile 32x64.
// SSTR=16 (no padding): fragment LDS.64s cover exactly 256B contiguous ->
// conflict-free; cp.async stores fully linear.
#define KT 16
#define ARRE (128*KT)        // elems per array (2048)
#define ARRB (ARRE*2)        // bytes per array (4096)
#define STGB (4*ARRB)        // bytes per stage (16384)
#define NSTG 5
#define GSMEM (NSTG*STGB)    // 81920
template <int MODE>
__global__ __launch_bounds__(256, 2) void gemm_mma(
    float* __restrict__ Cext,
    const float* __restrict__ dtbH0, const float* __restrict__ dtbH1,
    const float* __restrict__ dtbV0, const float* __restrict__ dtbV1,
    const int* __restrict__ rowmap)
{
    extern __shared__ __align__(16) __nv_bfloat16 sm[];

    const int K = (MODE == 2) ? 1024 : 256;
    int tid = threadIdx.x, lane = tid & 31, wid = tid >> 5;
    int warp_m = wid & 3, warp_n = wid >> 2;
    int qr = lane >> 2, qc = lane & 3;
    int bn = blockIdx.x, bm = blockIdx.y, z = blockIdx.z;

    const __nv_bfloat16 *Ah, *Al, *Bh, *Bl;
    if (MODE == 0) {
        Ah = g_ax_hi + (size_t)z * AXSZ; Al = g_ax_lo + (size_t)z * AXSZ;
        Bh = g_wi_hi + (size_t)z * WISZ; Bl = g_wi_lo + (size_t)z * WISZ;
    } else if (MODE == 1) {
        Ah = g_y_hi + (size_t)z * YSZ;   Al = g_y_lo + (size_t)z * YSZ;
        int bs = z ^ 1;   // reference swaps F/B output weights
        Bh = g_wo_hi + (size_t)bs * WOSZ; Bl = g_wo_lo + (size_t)bs * WOSZ;
    } else {
        Ah = g_cat_hi; Al = g_cat_lo; Bh = g_wf_hi; Bl = g_wf_lo;
    }

    // copy mapping: thread -> (row = tid>>1, 16B half = tid&1); 4 cp16/tile
    int row16 = tid >> 1;
    int half8 = (tid & 1) << 3;                    // element offset 0/8
    size_t aoff = (size_t)(bm * 128 + row16) * K + half8;
    size_t boff = (size_t)(bn * 128 + row16) * K + half8;
    uint32_t soffB = (uint32_t)(row16 * (KT * 2) + (tid & 1) * 16);
    uint32_t sbu = (uint32_t)__cvta_generic_to_shared(sm);

    float acc[2][8][4];
#pragma unroll
    for (int i = 0; i < 2; i++)
#pragma unroll
        for (int j = 0; j < 8; j++)
#pragma unroll
            for (int k = 0; k < 4; k++) acc[i][j][k] = 0.f;

    const int nk = K >> 4;

#define COPY_TILE(tile, slot) do {                                  \
        uint32_t st_ = sbu + (slot) * STGB;                         \
        size_t ko_ = (size_t)(tile) * KT;                           \
        cp16(st_ + 0*ARRB + soffB, Ah + aoff + ko_);                \
        cp16(st_ + 1*ARRB + soffB, Al + aoff + ko_);                \
        cp16(st_ + 2*ARRB + soffB, Bh + boff + ko_);                \
        cp16(st_ + 3*ARRB + soffB, Bl + boff + ko_);                \
        cpcommit();                                                 \
    } while (0)

    // prologue: stages 0..3
#pragma unroll
    for (int p = 0; p < 4; p++) COPY_TILE(p, p);

    int slot = 0, slot4 = 4;
    for (int kt = 0; kt < nk; kt++) {
        cpwait3();
        __syncthreads();
        if (kt + 4 < nk) {
            COPY_TILE(kt + 4, slot4);
            if (++slot4 == NSTG) slot4 = 0;
        }
        const __nv_bfloat16* base = sm + slot * (STGB / 2);
        const __nv_bfloat16* As  = base;
        const __nv_bfloat16* Als = base + ARRE;
        const __nv_bfloat16* Bs  = base + 2 * ARRE;
        const __nv_bfloat16* Bls = base + 3 * ARRE;

        int kof = qc * 4;
        uint32_t ah[2][4], al[2][4];
#pragma unroll
        for (int mt = 0; mt < 2; mt++) {
            int ar = (warp_m * 32 + mt * 16 + qr) * KT + kof;
            uint2 h0 = *(const uint2*)&As[ar];
            uint2 h1 = *(const uint2*)&As[ar + 8 * KT];
            ah[mt][0] = h0.x; ah[mt][1] = h1.x; ah[mt][2] = h0.y; ah[mt][3] = h1.y;
            uint2 l0 = *(const uint2*)&Als[ar];
            uint2 l1 = *(const uint2*)&Als[ar + 8 * KT];
            al[mt][0] = l0.x; al[mt][1] = l1.x; al[mt][2] = l0.y; al[mt][3] = l1.y;
        }
#pragma unroll
        for (int g = 0; g < 2; g++) {
            uint32_t bh[4][2], bl[4][2];
#pragma unroll
            for (int j = 0; j < 4; j++) {
                int nr = (warp_n * 64 + (g * 4 + j) * 8 + qr) * KT + kof;
                uint2 bb = *(const uint2*)&Bs[nr];
                bh[j][0] = bb.x; bh[j][1] = bb.y;
                uint2 bc = *(const uint2*)&Bls[nr];
                bl[j][0] = bc.x; bl[j][1] = bc.y;
            }
#pragma unroll
            for (int mt = 0; mt < 2; mt++)
#pragma unroll
                for (int j = 0; j < 4; j++)
                    MMA_BF16(acc[mt][g*4+j], ah[mt][0],ah[mt][1],ah[mt][2],ah[mt][3],
                             bh[j][0], bh[j][1]);
#pragma unroll
            for (int mt = 0; mt < 2; mt++)
#pragma unroll
                for (int j = 0; j < 4; j++)
                    MMA_BF16(acc[mt][g*4+j], ah[mt][0],ah[mt][1],ah[mt][2],ah[mt][3],
                             bl[j][0], bl[j][1]);
#pragma unroll
            for (int mt = 0; mt < 2; mt++)
#pragma unroll
                for (int j = 0; j < 4; j++)
                    MMA_BF16(acc[mt][g*4+j], al[mt][0],al[mt][1],al[mt][2],al[mt][3],
                             bh[j][0], bh[j][1]);
        }
        __syncthreads();
        if (++slot == NSTG) slot = 0;
    }
#undef COPY_TILE

    // ---------------- epilogue ----------------
#pragma unroll
    for (int mt = 0; mt < 2; mt++) {
        int r0 = bm * 128 + warp_m * 32 + mt * 16 + qr;
#pragma unroll
        for (int nt = 0; nt < 8; nt++) {
            int c = bn * 128 + warp_n * 64 + nt * 8 + qc * 2;
            const float* a = acc[mt][nt];
#pragma unroll
            for (int rr = 0; rr < 2; rr++) {
                int r = r0 + rr * 8;
                float v0 = a[rr * 2 + 0], v1 = a[rr * 2 + 1];
                if (MODE == 0) {
                    float* C = g_zx + (size_t)z * ZXSZ + (size_t)r * NPROJ2;
                    float vv[2] = {v0, v1};
#pragma unroll
                    for (int h = 0; h < 2; h++) {
                        int cc = c + h;
                        if (cc < NPROJ2) {
                            int dI = (cc >= DPROJ);
                            int rI = cc - dI * DPROJ;
                            float o;
                            if (rI < 2 * DINN + 2 * NSS) o = siluf(vv[h]);
                            else {
                                const float* dtb = z ? (dI ? dtbV1 : dtbV0)
                                                     : (dI ? dtbH1 : dtbH0);
                                o = softplusf(vv[h] + dtb[rI - (2 * DINN + 2 * NSS)]);
                            }
                            C[cc] = o;
                        }
                    }
                } else if (MODE == 1) {
                    int orow = r;
                    if (z >= 2) orow = (r & ~(LL - 1)) | rowmap[r];
                    size_t rb = (size_t)orow * 1024 + z * 256 + kperm(c);
                    float o0 = siluf(v0), o1 = siluf(v1);
                    __nv_bfloat16 h0, l0, h1, l1;
                    split_bf16(o0, h0, l0); split_bf16(o1, h1, l1);
                    __nv_bfloat162 ph; ph.x = h0; ph.y = h1;
                    __nv_bfloat162 pl; pl.x = l0; pl.y = l1;
                    *(__nv_bfloat162*)&g_cat_hi[rb] = ph;
                    *(__nv_bfloat162*)&g_cat_lo[rb] = pl;
                } else {
                    float2 o; o.x = v0; o.y = v1;
                    *(float2*)&Cext[(size_t)r * 256 + c] = o;
                }
            }
        }
    }
}

// ---------------- scan kernels ----------------
struct SP { const float* alog[4]; const float* Dp[4]; };

__global__ __launch_bounds__(64) void scan_pass1(SP sp)
{
    __shared__ float bc[QC][20];
    __shared__ float xs[SUBC][HPP];

    int chunk = blockIdx.x;
    int b = blockIdx.y >> 2, head = blockIdx.y & 3, dir = blockIdx.z;
    int tid = threadIdx.x;

    const float* base = g_zx + (size_t)(dir >> 1) * ZXSZ;
    int off = (dir & 1) * DPROJ;
    bool rev = (dir & 1);
    long t0 = rev ? (long)(LL - 1 - chunk * QC) : (long)(chunk * QC);
    long rstride = rev ? -(long)NPROJ2 : (long)NPROJ2;
    const float* row0 = base + ((long)b * LL + t0) * NPROJ2 + off;

    for (int idx = tid; idx < QC * 20; idx += 64) {
        int st = idx / 20, q = idx - st * 20;
        bc[st][q] = row0[(long)st * rstride + 2 * DINN + q];
    }

    float a = -__expf(sp.alog[dir][head]);
    float s[NSS];
#pragma unroll
    for (int n = 0; n < NSS; n++) s[n] = 0.f;
    float Pd = 1.f;

    const float* xbase = row0 + DINN + head * HPP;
    for (int sub = 0; sub < QC; sub += SUBC) {
        __syncthreads();
        for (int idx = tid; idx < SUBC * 16; idx += 64) {
            int st = idx >> 4, v = (idx & 15) * 4;
            *(float4*)&xs[st][v] = *(const float4*)(xbase + (long)(sub + st) * rstride + v);
        }
        __syncthreads();
        for (int st = 0; st < SUBC; st++) {
            int t = sub + st;
            float dt = bc[t][16 + head];
            float dA = __expf(dt * a);
            float dtx = dt * xs[st][tid];
            Pd *= dA;
            float4 b0 = *(const float4*)&bc[t][0];
            float4 b1 = *(const float4*)&bc[t][4];
            s[0] = fmaf(dA, s[0], b0.x * dtx);
            s[1] = fmaf(dA, s[1], b0.y * dtx);
            s[2] = fmaf(dA, s[2], b0.z * dtx);
            s[3] = fmaf(dA, s[3], b0.w * dtx);
            s[4] = fmaf(dA, s[4], b1.x * dtx);
            s[5] = fmaf(dA, s[5], b1.y * dtx);
            s[6] = fmaf(dA, s[6], b1.z * dtx);
            s[7] = fmaf(dA, s[7], b1.w * dtx);
        }
    }

    int u = (dir * BB + b) * NHH + head;
    size_t sb = ((size_t)u * NCHUNK + chunk) * (HPP * NSS) + (size_t)tid * NSS;
#pragma unroll
    for (int n = 0; n < NSS; n++) g_cstate[sb + n] = s[n];
    if (tid == 0) g_cdecay[u * NCHUNK + chunk] = Pd;
}

__global__ __launch_bounds__(512) void scan_pass2()
{
    __shared__ float dec[NCHUNK];
    int u = blockIdx.x, tid = threadIdx.x;
    if (tid < NCHUNK) dec[tid] = g_cdecay[u * NCHUNK + tid];
    __syncthreads();
    float h = 0.f;
    size_t base = (size_t)u * NCHUNK * (HPP * NSS) + tid;
    for (int cb = 0; cb < NCHUNK / 8; cb++) {
        float v[8];
#pragma unroll
        for (int j = 0; j < 8; j++)
            v[j] = g_cstate[base + (size_t)(cb * 8 + j) * (HPP * NSS)];
#pragma unroll
        for (int j = 0; j < 8; j++) {
            size_t idx = base + (size_t)(cb * 8 + j) * (HPP * NSS);
            g_istate[idx] = h;
            h = dec[cb * 8 + j] * h + v[j];
        }
    }
}

__global__ __launch_bounds__(64) void scan_pass3(SP sp)
{
    __shared__ float bc[QC][20];
    __shared__ float xs[SUBC][HPP];
    __shared__ float zs[SUBC][HPP];

    int chunk = blockIdx.x;
    int b = blockIdx.y >> 2, head = blockIdx.y & 3, dir = blockIdx.z;
    int tid = threadIdx.x;

    const float* base = g_zx + (size_t)(dir >> 1) * ZXSZ;
    int off = (dir & 1) * DPROJ;
    bool rev = (dir & 1);
    long t0 = rev ? (long)(LL - 1 - chunk * QC) : (long)(chunk * QC);
    long rstride = rev ? -(long)NPROJ2 : (long)NPROJ2;
    const float* row0 = base + ((long)b * LL + t0) * NPROJ2 + off;

    for (int idx = tid; idx < QC * 20; idx += 64) {
        int st = idx / 20, q = idx - st * 20;
        bc[st][q] = row0[(long)st * rstride + 2 * DINN + q];
    }

    float a = -__expf(sp.alog[dir][head]);
    float Dh = sp.Dp[dir][head];

    int u = (dir * BB + b) * NHH + head;
    size_t sb = ((size_t)u * NCHUNK + chunk) * (HPP * NSS) + (size_t)tid * NSS;
    float s[NSS];
#pragma unroll
    for (int n = 0; n < NSS; n++) s[n] = g_istate[sb + n];

    int ycol = kperm(head * HPP + tid);
    size_t ybase = (size_t)dir * YSZ + ((size_t)b * LL + (size_t)t0) * DINN + ycol;
    long ystride = rev ? -(long)DINN : (long)DINN;

    const float* xbase = row0 + DINN + head * HPP;
    const float* zbase = row0 + head * HPP;

    for (int sub = 0; sub < QC; sub += SUBC) {
        __syncthreads();
        for (int idx = tid; idx < SUBC * 16; idx += 64) {
            int st = idx >> 4, v = (idx & 15) * 4;
            *(float4*)&xs[st][v] = *(const float4*)(xbase + (long)(sub + st) * rstride + v);
            *(float4*)&zs[st][v] = *(const float4*)(zbase + (long)(sub + st) * rstride + v);
        }
        __syncthreads();
        for (int st = 0; st < SUBC; st++) {
            int t = sub + st;
            float dt = bc[t][16 + head];
            float dA = __expf(dt * a);
            float xv = xs[st][tid];
            float dtx = dt * xv;
            float4 b0 = *(const float4*)&bc[t][0];
            float4 b1 = *(const float4*)&bc[t][4];
            float4 c0 = *(const float4*)&bc[t][8];
            float4 c1 = *(const float4*)&bc[t][12];
            s[0] = fmaf(dA, s[0], b0.x * dtx);
            s[1] = fmaf(dA, s[1], b0.y * dtx);
            s[2] = fmaf(dA, s[2], b0.z * dtx);
            s[3] = fmaf(dA, s[3], b0.w * dtx);
            s[4] = fmaf(dA, s[4], b1.x * dtx);
            s[5] = fmaf(dA, s[5], b1.y * dtx);
            s[6] = fmaf(dA, s[6], b1.z * dtx);
            s[7] = fmaf(dA, s[7], b1.w * dtx);
            float y0 = fmaf(s[0], c0.x, fmaf(s[2], c0.z, fmaf(s[4], c1.x, s[6] * c1.z)));
            float y1 = fmaf(s[1], c0.y, fmaf(s[3], c0.w, fmaf(s[5], c1.y, s[7] * c1.w)));
            float outv = fmaf(Dh, xv, y0 + y1) * zs[st][tid];
            __nv_bfloat16 h, l; split_bf16(outv, h, l);
            size_t yo = ybase + (long)t * ystride;
            g_y_hi[yo] = h;
            g_y_lo[yo] = l;
        }
    }
}

// ---------------- launch ----------------
extern "C" void kernel_launch(void* const* d_in, const int* in_sizes, int n_in,
                              void* d_out, int out_size)
{
    const float *xH, *xV, *WinH, *WinV, *WoHF, *WoHB, *WoVF, *WoVB, *Wout;
    const float *dtb[4], *alog[4], *Dp[4];
    const int* v2h;

    if (in_sizes[0] == 4) {
        alog[1] = (const float*)d_in[0];  alog[0] = (const float*)d_in[1];
        alog[3] = (const float*)d_in[2];  alog[2] = (const float*)d_in[3];
        Dp[1]   = (const float*)d_in[4];  Dp[0]   = (const float*)d_in[5];
        Dp[3]   = (const float*)d_in[6];  Dp[2]   = (const float*)d_in[7];
        WinH = (const float*)d_in[8];     WinV = (const float*)d_in[9];
        Wout = (const float*)d_in[10];
        WoHB = (const float*)d_in[11];    WoHF = (const float*)d_in[12];
        WoVB = (const float*)d_in[13];    WoVF = (const float*)d_in[14];
        dtb[1] = (const float*)d_in[15];  dtb[0] = (const float*)d_in[16];
        dtb[3] = (const float*)d_in[17];  dtb[2] = (const float*)d_in[18];
        v2h = (const int*)d_in[19];
        xH = (const float*)d_in[20];      xV = (const float*)d_in[21];
    } else if (in_sizes[4] == 65536) {
        xH = (const float*)d_in[0];  xV = (const float*)d_in[1];
        WinH = (const float*)d_in[2]; WinV = (const float*)d_in[3];
        WoHF = (const float*)d_in[4]; WoHB = (const float*)d_in[5];
        WoVF = (const float*)d_in[6]; WoVB = (const float*)d_in[7];
        Wout = (const float*)d_in[8];
        for (int d = 0; d < 4; d++) {
            dtb[d]  = (const float*)d_in[9 + 3 * d + 0];
            alog[d] = (const float*)d_in[9 + 3 * d + 1];
            Dp[d]   = (const float*)d_in[9 + 3 * d + 2];
        }
        v2h = (const int*)d_in[21];
    } else {
        xH = (const float*)d_in[0];  xV = (const float*)d_in[1];
        WinH = (const float*)d_in[2]; WinV = (const float*)d_in[3];
        for (int d = 0; d < 4; d++) {
            dtb[d]  = (const float*)d_in[4 + d];
            alog[d] = (const float*)d_in[8 + d];
            Dp[d]   = (const float*)d_in[12 + d];
        }
        WoHF = (const float*)d_in[16]; WoHB = (const float*)d_in[17];
        WoVF = (const float*)d_in[18]; WoVB = (const float*)d_in[19];
        Wout = (const float*)d_in[20];
        v2h = (const int*)d_in[21];
    }

    SP sp;
    for (int d = 0; d < 4; d++) { sp.alog[d] = alog[d]; sp.Dp[d] = Dp[d]; }

    cudaFuncSetAttribute(gemm_mma<0>, cudaFuncAttributeMaxDynamicSharedMemorySize, GSMEM);
    cudaFuncSetAttribute(gemm_mma<1>, cudaFuncAttributeMaxDynamicSharedMemorySize, GSMEM);
    cudaFuncSetAttribute(gemm_mma<2>, cudaFuncAttributeMaxDynamicSharedMemorySize, GSMEM);

    // launches 0,1: prep for gemm<0>
    conv_all<<<dim3((int)(AXSZ / 4 / 256), 2), 256>>>(xH, xV);
    wsplit_in<<<2 * 1152, 256>>>(WinH, WinV);

    // launch 2 (profiler lands here): in-proj GEMM, both z merged
    gemm_mma<0><<<dim3(9, MM / 128, 2), 256, GSMEM>>>(
        nullptr, dtb[0], dtb[1], dtb[2], dtb[3], nullptr);

    // remaining weight prep
    wsplit_rest<<<2048, 256>>>(WoHF, WoHB, WoVF, WoVB, Wout);

    // chunked selective scan
    scan_pass1<<<dim3(NCHUNK, BB * NHH, 4), 64>>>(sp);
    scan_pass2<<<NUNIT, 512>>>();
    scan_pass3<<<dim3(NCHUNK, BB * NHH, 4), 64>>>(sp);

    // out-projections (all 4 dirs batched via z): silu + v2h scatter -> cat hi/lo
    gemm_mma<1><<<dim3(2, MM / 128, 4), 256, GSMEM>>>(
        nullptr, nullptr, nullptr, nullptr, nullptr, v2h);

    // final projection
    gemm_mma<2><<<dim3(2, MM / 128, 1), 256, GSMEM>>>(
        (float*)d_out, nullptr, nullptr, nullptr, nullptr, nullptr);
}

// round 17
// speedup vs baseline: 1.3362x; 1.2466x over previous
#include <cuda_runtime.h>
#include <cuda_bf16.h>
#include <cstdint>

#define BB 2
#define LL 8192
#define DMM 256
#define NHH 4
#define HPP 64
#define NSS 8
#define DINN 256
#define DPROJ 532
#define NPROJ2 1064
#define QC 128
#define SUBC 64
#define NCHUNK 64
#define NUNIT 32
#define MM (BB*LL)

#define AXSZ ((size_t)MM*DMM)
#define ZXSZ ((size_t)MM*NPROJ2)
#define YSZ  ((size_t)MM*DINN)
#define WISZ ((size_t)1152*256)
#define WOSZ ((size_t)256*256)
#define WFSZ ((size_t)256*1024)

// ---------------- device scratch ----------------
__device__ float g_zx[2*ZXSZ];
__device__ __nv_bfloat16 g_ax_hi[2*AXSZ], g_ax_lo[2*AXSZ];
__device__ __nv_bfloat16 g_y_hi[4*YSZ],  g_y_lo[4*YSZ];
__device__ __nv_bfloat16 g_cat_hi[(size_t)MM*1024], g_cat_lo[(size_t)MM*1024];
__device__ __nv_bfloat16 g_wi_hi[2*WISZ], g_wi_lo[2*WISZ];
__device__ __nv_bfloat16 g_wo_hi[4*WOSZ], g_wo_lo[4*WOSZ];
__device__ __nv_bfloat16 g_wf_hi[WFSZ],   g_wf_lo[WFSZ];
__device__ float g_cstate[(size_t)NUNIT*NCHUNK*HPP*NSS];
__device__ float g_istate[(size_t)NUNIT*NCHUNK*HPP*NSS];
__device__ float g_cdecay[NUNIT*NCHUNK];

// ---------------- helpers ----------------
__device__ __forceinline__ float siluf(float x) { return x / (1.f + __expf(-x)); }
__device__ __forceinline__ float softplusf(float x) {
    return fmaxf(x, 0.f) + log1pf(__expf(-fabsf(x)));
}
__device__ __forceinline__ void split_bf16(float v, __nv_bfloat16& hi, __nv_bfloat16& lo) {
    hi = __float2bfloat16(v);
    lo = __float2bfloat16(v - __bfloat162float(hi));
}
// XOR swizzle at 16B-chunk granularity over 128B lines.
// r = logical row (0..127), c = 16B chunk within 64B row (0..3).
// Conflict-free for ldmatrix 8-row tile reads AND 4-chunk/2-row cp.async stores.
__device__ __forceinline__ uint32_t swz(int r, int c) {
    return (uint32_t)((r >> 1) * 128 + (((((r & 1) << 2) | c) ^ ((r >> 1) & 7)) << 4));
}

#define MMA_BF16(d, a0,a1,a2,a3, b0,b1) \
    asm volatile("mma.sync.aligned.m16n8k16.row.col.f32.bf16.bf16.f32 " \
        "{%0,%1,%2,%3}, {%4,%5,%6,%7}, {%8,%9}, {%0,%1,%2,%3};" \
        : "+f"(d[0]),"+f"(d[1]),"+f"(d[2]),"+f"(d[3]) \
        : "r"(a0),"r"(a1),"r"(a2),"r"(a3), "r"(b0),"r"(b1))

#define LDSM4(d0,d1,d2,d3,a) \
    asm volatile("ldmatrix.sync.aligned.m8n8.x4.shared.b16 {%0,%1,%2,%3}, [%4];" \
        : "=r"(d0),"=r"(d1),"=r"(d2),"=r"(d3) : "r"(a))

__device__ __forceinline__ void cp16(uint32_t saddr, const void* g) {
    asm volatile("cp.async.cg.shared.global [%0], [%1], 16;" :: "r"(saddr), "l"(g));
}
__device__ __forceinline__ void cpcommit() {
    asm volatile("cp.async.commit_group;" ::: "memory");
}
__device__ __forceinline__ void cpwait0() {
    asm volatile("cp.async.wait_group 0;" ::: "memory");
}

// ---------------- prep kernels (plain row-major outputs) ----------------
__global__ void conv_all(const float* __restrict__ xH, const float* __restrict__ xV) {
    int sel = blockIdx.y;
    const float* src = sel ? xV : xH;
    size_t i = ((size_t)blockIdx.x * blockDim.x + threadIdx.x) * 4;
    if (i >= AXSZ) return;
    float4 v = *(const float4*)(src + i);
    __nv_bfloat16* ph = g_ax_hi + (size_t)sel * AXSZ + i;
    __nv_bfloat16* pl = g_ax_lo + (size_t)sel * AXSZ + i;
    float a[4] = {v.x, v.y, v.z, v.w};
#pragma unroll
    for (int j = 0; j < 4; j++) { __nv_bfloat16 h, l; split_bf16(a[j], h, l); ph[j] = h; pl[j] = l; }
}

__device__ __forceinline__ void wsplit_one(
    const float* __restrict__ W, __nv_bfloat16* dh, __nv_bfloat16* dl,
    int K, int N, int idx)
{
    int n = idx / K, k = idx - n * K;
    float v = (n < N) ? W[(size_t)k * N + n] : 0.f;
    __nv_bfloat16 h, l; split_bf16(v, h, l);
    dh[idx] = h; dl[idx] = l;
}

__global__ void wsplit_in(const float* __restrict__ WinH, const float* __restrict__ WinV) {
    int bx = blockIdx.x;
    int sub = (bx >= 1152); if (sub) bx -= 1152;
    int idx = bx * 256 + threadIdx.x;
    wsplit_one(sub ? WinV : WinH, g_wi_hi + (size_t)sub * WISZ,
               g_wi_lo + (size_t)sub * WISZ, 256, NPROJ2, idx);
}

__global__ void wsplit_rest(const float* __restrict__ W0, const float* __restrict__ W1,
                            const float* __restrict__ W2, const float* __restrict__ W3,
                            const float* __restrict__ Wf) {
    int bx = blockIdx.x;
    if (bx < 1024) {
        int sub = bx >> 8;
        const float* W = (sub == 0) ? W0 : (sub == 1) ? W1 : (sub == 2) ? W2 : W3;
        int idx = (bx & 255) * 256 + threadIdx.x;
        wsplit_one(W, g_wo_hi + (size_t)sub * WOSZ, g_wo_lo + (size_t)sub * WOSZ,
                   256, 256, idx);
    } else {
        int idx = (bx - 1024) * 256 + threadIdx.x;
        wsplit_one(Wf, g_wf_hi, g_wf_lo, 1024, 256, idx);
    }
}

// ---------------- split-bf16 ldmatrix GEMM, KT=32, 2-stage cp.async ------
// CTA tile 128x128, 8 warps (4 M x 2 N), warp tile 32x64.
// Per stage: 4 arrays (Ah, Al, Bh, Bl) x 128 rows x 64B = 32 KB.
#define ARR8K 8192
#define STG 32768
#define GSMEM (2*STG)
template <int MODE>
__global__ __launch_bounds__(256, 2) void gemm_mma(
    float* __restrict__ Cext,
    const float* __restrict__ dtbH0, const float* __restrict__ dtbH1,
    const float* __restrict__ dtbV0, const float* __restrict__ dtbV1,
    const int* __restrict__ rowmap)
{
    extern __shared__ __align__(16) char sm[];
    uint32_t sbu = (uint32_t)__cvta_generic_to_shared(sm);

    const int K = (MODE == 2) ? 1024 : 256;
    int tid = threadIdx.x, lane = tid & 31, wid = tid >> 5;
    int warp_m = wid & 3, warp_n = wid >> 2;
    int qr = lane >> 2, qc = lane & 3;
    int bn = blockIdx.x, bm = blockIdx.y, z = blockIdx.z;

    const __nv_bfloat16 *Ah, *Al, *Bh, *Bl;
    if (MODE == 0) {
        Ah = g_ax_hi + (size_t)z * AXSZ; Al = g_ax_lo + (size_t)z * AXSZ;
        Bh = g_wi_hi + (size_t)z * WISZ; Bl = g_wi_lo + (size_t)z * WISZ;
    } else if (MODE == 1) {
        Ah = g_y_hi + (size_t)z * YSZ;   Al = g_y_lo + (size_t)z * YSZ;
        int bs = z ^ 1;   // reference swaps F/B output weights
        Bh = g_wo_hi + (size_t)bs * WOSZ; Bl = g_wo_lo + (size_t)bs * WOSZ;
    } else {
        Ah = g_cat_hi; Al = g_cat_lo; Bh = g_wf_hi; Bl = g_wf_lo;
    }
    Ah += (size_t)(bm * 128) * K;  Al += (size_t)(bm * 128) * K;
    Bh += (size_t)(bn * 128) * K;  Bl += (size_t)(bn * 128) * K;

    // copy mapping: 512 16B-chunks per array; thread handles chunks tid, tid+256
    uint32_t so0 = swz(tid >> 2, tid & 3);
    uint32_t so1 = so0 + 4096;                       // row+64 -> +4096 (linear)
    size_t ga0 = (size_t)(tid >> 2) * K + (tid & 3) * 8;
    size_t ga1 = ga0 + (size_t)64 * K;

    // fragment base addresses (stage 0); +1024 per +16 rows; ^32 for ks=1
    uint32_t aswz = swz(warp_m * 32 + (lane & 15), lane >> 4);
    uint32_t bswz = swz(warp_n * 64 + (lane & 7) + ((lane & 16) >> 1), (lane >> 3) & 1);
    uint32_t adrAh = sbu + aswz;
    uint32_t adrAl = sbu + ARR8K + aswz;
    uint32_t adrBh = sbu + 2 * ARR8K + bswz;
    uint32_t adrBl = sbu + 3 * ARR8K + bswz;

    float acc[2][8][4];
#pragma unroll
    for (int i = 0; i < 2; i++)
#pragma unroll
        for (int j = 0; j < 8; j++)
#pragma unroll
            for (int k = 0; k < 4; k++) acc[i][j][k] = 0.f;

    const int nk = K >> 5;

#define COPY_TILE(tile, sOff) do {                                    \
        uint32_t st_ = sbu + (sOff);                                  \
        size_t ko_ = (size_t)(tile) * 32;                             \
        cp16(st_ + so0,             Ah + ga0 + ko_);                  \
        cp16(st_ + so1,             Ah + ga1 + ko_);                  \
        cp16(st_ + ARR8K + so0,     Al + ga0 + ko_);                  \
        cp16(st_ + ARR8K + so1,     Al + ga1 + ko_);                  \
        cp16(st_ + 2*ARR8K + so0,   Bh + ga0 + ko_);                  \
        cp16(st_ + 2*ARR8K + so1,   Bh + ga1 + ko_);                  \
        cp16(st_ + 3*ARR8K + so0,   Bl + ga0 + ko_);                  \
        cp16(st_ + 3*ARR8K + so1,   Bl + ga1 + ko_);                  \
        cpcommit();                                                   \
    } while (0)

    COPY_TILE(0, 0);

    for (int kt = 0; kt < nk; kt++) {
        uint32_t sOff = (kt & 1) * STG;
        cpwait0();
        __syncthreads();
        if (kt + 1 < nk) COPY_TILE(kt + 1, (sOff ^ STG));

#pragma unroll
        for (int ks = 0; ks < 2; ks++) {
            uint32_t xk = ks << 5;
            uint32_t ah[8], al[8];
            LDSM4(ah[0],ah[1],ah[2],ah[3], (adrAh + sOff) ^ xk);
            LDSM4(ah[4],ah[5],ah[6],ah[7], (adrAh + 1024 + sOff) ^ xk);
            LDSM4(al[0],al[1],al[2],al[3], (adrAl + sOff) ^ xk);
            LDSM4(al[4],al[5],al[6],al[7], (adrAl + 1024 + sOff) ^ xk);
#pragma unroll
            for (int h = 0; h < 2; h++) {
                uint32_t bh[8], bl[8];
                uint32_t bo = h * 2048 + sOff;
                LDSM4(bh[0],bh[1],bh[2],bh[3], (adrBh + bo) ^ xk);
                LDSM4(bh[4],bh[5],bh[6],bh[7], (adrBh + bo + 1024) ^ xk);
                LDSM4(bl[0],bl[1],bl[2],bl[3], (adrBl + bo) ^ xk);
                LDSM4(bl[4],bl[5],bl[6],bl[7], (adrBl + bo + 1024) ^ xk);
#pragma unroll
                for (int mt = 0; mt < 2; mt++)
#pragma unroll
                    for (int j = 0; j < 4; j++)
                        MMA_BF16(acc[mt][h*4+j], ah[mt*4],ah[mt*4+1],ah[mt*4+2],ah[mt*4+3],
                                 bh[2*j], bh[2*j+1]);
#pragma unroll
                for (int mt = 0; mt < 2; mt++)
#pragma unroll
                    for (int j = 0; j < 4; j++)
                        MMA_BF16(acc[mt][h*4+j], ah[mt*4],ah[mt*4+1],ah[mt*4+2],ah[mt*4+3],
                                 bl[2*j], bl[2*j+1]);
#pragma unroll
                for (int mt = 0; mt < 2; mt++)
#pragma unroll
                    for (int j = 0; j < 4; j++)
                        MMA_BF16(acc[mt][h*4+j], al[mt*4],al[mt*4+1],al[mt*4+2],al[mt*4+3],
                                 bh[2*j], bh[2*j+1]);
            }
        }
        __syncthreads();
    }
#undef COPY_TILE

    // ---------------- epilogue ----------------
#pragma unroll
    for (int mt = 0; mt < 2; mt++) {
        int r0 = bm * 128 + warp_m * 32 + mt * 16 + qr;
#pragma unroll
        for (int nt = 0; nt < 8; nt++) {
            int c = bn * 128 + warp_n * 64 + nt * 8 + qc * 2;
            const float* a = acc[mt][nt];
#pragma unroll
            for (int rr = 0; rr < 2; rr++) {
                int r = r0 + rr * 8;
                float v0 = a[rr * 2 + 0], v1 = a[rr * 2 + 1];
                if (MODE == 0) {
                    float* C = g_zx + (size_t)z * ZXSZ + (size_t)r * NPROJ2;
                    float vv[2] = {v0, v1};
#pragma unroll
                    for (int h = 0; h < 2; h++) {
                        int cc = c + h;
                        if (cc < NPROJ2) {
                            int dI = (cc >= DPROJ);
                            int rI = cc - dI * DPROJ;
                            float o;
                            if (rI < 2 * DINN + 2 * NSS) o = siluf(vv[h]);
                            else {
                                const float* dtb = z ? (dI ? dtbV1 : dtbV0)
                                                     : (dI ? dtbH1 : dtbH0);
                                o = softplusf(vv[h] + dtb[rI - (2 * DINN + 2 * NSS)]);
                            }
                            C[cc] = o;
                        }
                    }
                } else if (MODE == 1) {
                    int orow = r;
                    if (z >= 2) orow = (r & ~(LL - 1)) | rowmap[r];
                    size_t rb = (size_t)orow * 1024 + z * 256 + c;
                    float o0 = siluf(v0), o1 = siluf(v1);
                    __nv_bfloat16 h0, l0, h1, l1;
                    split_bf16(o0, h0, l0); split_bf16(o1, h1, l1);
                    __nv_bfloat162 ph; ph.x = h0; ph.y = h1;
                    __nv_bfloat162 pl; pl.x = l0; pl.y = l1;
                    *(__nv_bfloat162*)&g_cat_hi[rb] = ph;
                    *(__nv_bfloat162*)&g_cat_lo[rb] = pl;
                } else {
                    float2 o; o.x = v0; o.y = v1;
                    *(float2*)&Cext[(size_t)r * 256 + c] = o;
                }
            }
        }
    }
}

// ---------------- scan kernels ----------------
struct SP { const float* alog[4]; const float* Dp[4]; };

__global__ __launch_bounds__(64) void scan_pass1(SP sp)
{
    __shared__ float bc[QC][20];
    __shared__ float xs[SUBC][HPP];

    int chunk = blockIdx.x;
    int b = blockIdx.y >> 2, head = blockIdx.y & 3, dir = blockIdx.z;
    int tid = threadIdx.x;

    const float* base = g_zx + (size_t)(dir >> 1) * ZXSZ;
    int off = (dir & 1) * DPROJ;
    bool rev = (dir & 1);
    long t0 = rev ? (long)(LL - 1 - chunk * QC) : (long)(chunk * QC);
    long rstride = rev ? -(long)NPROJ2 : (long)NPROJ2;
    const float* row0 = base + ((long)b * LL + t0) * NPROJ2 + off;

    for (int idx = tid; idx < QC * 20; idx += 64) {
        int st = idx / 20, q = idx - st * 20;
        bc[st][q] = row0[(long)st * rstride + 2 * DINN + q];
    }

    float a = -__expf(sp.alog[dir][head]);
    float s[NSS];
#pragma unroll
    for (int n = 0; n < NSS; n++) s[n] = 0.f;
    float Pd = 1.f;

    const float* xbase = row0 + DINN + head * HPP;
    for (int sub = 0; sub < QC; sub += SUBC) {
        __syncthreads();
        for (int idx = tid; idx < SUBC * 16; idx += 64) {
            int st = idx >> 4, v = (idx & 15) * 4;
            *(float4*)&xs[st][v] = *(const float4*)(xbase + (long)(sub + st) * rstride + v);
        }
        __syncthreads();
        for (int st = 0; st < SUBC; st++) {
            int t = sub + st;
            float dt = bc[t][16 + head];
            float dA = __expf(dt * a);
            float dtx = dt * xs[st][tid];
            Pd *= dA;
            float4 b0 = *(const float4*)&bc[t][0];
            float4 b1 = *(const float4*)&bc[t][4];
            s[0] = fmaf(dA, s[0], b0.x * dtx);
            s[1] = fmaf(dA, s[1], b0.y * dtx);
            s[2] = fmaf(dA, s[2], b0.z * dtx);
            s[3] = fmaf(dA, s[3], b0.w * dtx);
            s[4] = fmaf(dA, s[4], b1.x * dtx);
            s[5] = fmaf(dA, s[5], b1.y * dtx);
            s[6] = fmaf(dA, s[6], b1.z * dtx);
            s[7] = fmaf(dA, s[7], b1.w * dtx);
        }
    }

    int u = (dir * BB + b) * NHH + head;
    size_t sb = ((size_t)u * NCHUNK + chunk) * (HPP * NSS) + (size_t)tid * NSS;
#pragma unroll
    for (int n = 0; n < NSS; n++) g_cstate[sb + n] = s[n];
    if (tid == 0) g_cdecay[u * NCHUNK + chunk] = Pd;
}

__global__ __launch_bounds__(512) void scan_pass2()
{
    __shared__ float dec[NCHUNK];
    int u = blockIdx.x, tid = threadIdx.x;
    if (tid < NCHUNK) dec[tid] = g_cdecay[u * NCHUNK + tid];
    __syncthreads();
    float h = 0.f;
    size_t base = (size_t)u * NCHUNK * (HPP * NSS) + tid;
    for (int cb = 0; cb < NCHUNK / 8; cb++) {
        float v[8];
#pragma unroll
        for (int j = 0; j < 8; j++)
            v[j] = g_cstate[base + (size_t)(cb * 8 + j) * (HPP * NSS)];
#pragma unroll
        for (int j = 0; j < 8; j++) {
            size_t idx = base + (size_t)(cb * 8 + j) * (HPP * NSS);
            g_istate[idx] = h;
            h = dec[cb * 8 + j] * h + v[j];
        }
    }
}

__global__ __launch_bounds__(64) void scan_pass3(SP sp)
{
    __shared__ float bc[QC][20];
    __shared__ float xs[SUBC][HPP];
    __shared__ float zs[SUBC][HPP];

    int chunk = blockIdx.x;
    int b = blockIdx.y >> 2, head = blockIdx.y & 3, dir = blockIdx.z;
    int tid = threadIdx.x;

    const float* base = g_zx + (size_t)(dir >> 1) * ZXSZ;
    int off = (dir & 1) * DPROJ;
    bool rev = (dir & 1);
    long t0 = rev ? (long)(LL - 1 - chunk * QC) : (long)(chunk * QC);
    long rstride = rev ? -(long)NPROJ2 : (long)NPROJ2;
    const float* row0 = base + ((long)b * LL + t0) * NPROJ2 + off;

    for (int idx = tid; idx < QC * 20; idx += 64) {
        int st = idx / 20, q = idx - st * 20;
        bc[st][q] = row0[(long)st * rstride + 2 * DINN + q];
    }

    float a = -__expf(sp.alog[dir][head]);
    float Dh = sp.Dp[dir][head];

    int u = (dir * BB + b) * NHH + head;
    size_t sb = ((size_t)u * NCHUNK + chunk) * (HPP * NSS) + (size_t)tid * NSS;
    float s[NSS];
#pragma unroll
    for (int n = 0; n < NSS; n++) s[n] = g_istate[sb + n];

    size_t ybase = (size_t)dir * YSZ + ((size_t)b * LL + (size_t)t0) * DINN
                 + head * HPP + tid;
    long ystride = rev ? -(long)DINN : (long)DINN;

    const float* xbase = row0 + DINN + head * HPP;
    const float* zbase = row0 + head * HPP;

    for (int sub = 0; sub < QC; sub += SUBC) {
        __syncthreads();
        for (int idx = tid; idx < SUBC * 16; idx += 64) {
            int st = idx >> 4, v = (idx & 15) * 4;
            *(float4*)&xs[st][v] = *(const float4*)(xbase + (long)(sub + st) * rstride + v);
            *(float4*)&zs[st][v] = *(const float4*)(zbase + (long)(sub + st) * rstride + v);
        }
        __syncthreads();
        for (int st = 0; st < SUBC; st++) {
            int t = sub + st;
            float dt = bc[t][16 + head];
            float dA = __expf(dt * a);
            float xv = xs[st][tid];
            float dtx = dt * xv;
            float4 b0 = *(const float4*)&bc[t][0];
            float4 b1 = *(const float4*)&bc[t][4];
            float4 c0 = *(const float4*)&bc[t][8];
            float4 c1 = *(const float4*)&bc[t][12];
            s[0] = fmaf(dA, s[0], b0.x * dtx);
            s[1] = fmaf(dA, s[1], b0.y * dtx);
            s[2] = fmaf(dA, s[2], b0.z * dtx);
            s[3] = fmaf(dA, s[3], b0.w * dtx);
            s[4] = fmaf(dA, s[4], b1.x * dtx);
            s[5] = fmaf(dA, s[5], b1.y * dtx);
            s[6] = fmaf(dA, s[6], b1.z * dtx);
            s[7] = fmaf(dA, s[7], b1.w * dtx);
            float y0 = fmaf(s[0], c0.x, fmaf(s[2], c0.z, fmaf(s[4], c1.x, s[6] * c1.z)));
            float y1 = fmaf(s[1], c0.y, fmaf(s[3], c0.w, fmaf(s[5], c1.y, s[7] * c1.w)));
            float outv = fmaf(Dh, xv, y0 + y1) * zs[st][tid];
            __nv_bfloat16 h, l; split_bf16(outv, h, l);
            size_t yo = ybase + (long)t * ystride;
            g_y_hi[yo] = h;
            g_y_lo[yo] = l;
        }
    }
}

// ---------------- launch ----------------
extern "C" void kernel_launch(void* const* d_in, const int* in_sizes, int n_in,
                              void* d_out, int out_size)
{
    const float *xH, *xV, *WinH, *WinV, *WoHF, *WoHB, *WoVF, *WoVB, *Wout;
    const float *dtb[4], *alog[4], *Dp[4];
    const int* v2h;

    if (in_sizes[0] == 4) {
        alog[1] = (const float*)d_in[0];  alog[0] = (const float*)d_in[1];
        alog[3] = (const float*)d_in[2];  alog[2] = (const float*)d_in[3];
        Dp[1]   = (const float*)d_in[4];  Dp[0]   = (const float*)d_in[5];
        Dp[3]   = (const float*)d_in[6];  Dp[2]   = (const float*)d_in[7];
        WinH = (const float*)d_in[8];     WinV = (const float*)d_in[9];
        Wout = (const float*)d_in[10];
        WoHB = (const float*)d_in[11];    WoHF = (const float*)d_in[12];
        WoVB = (const float*)d_in[13];    WoVF = (const float*)d_in[14];
        dtb[1] = (const float*)d_in[15];  dtb[0] = (const float*)d_in[16];
        dtb[3] = (const float*)d_in[17];  dtb[2] = (const float*)d_in[18];
        v2h = (const int*)d_in[19];
        xH = (const float*)d_in[20];      xV = (const float*)d_in[21];
    } else if (in_sizes[4] == 65536) {
        xH = (const float*)d_in[0];  xV = (const float*)d_in[1];
        WinH = (const float*)d_in[2]; WinV = (const float*)d_in[3];
        WoHF = (const float*)d_in[4]; WoHB = (const float*)d_in[5];
        WoVF = (const float*)d_in[6]; WoVB = (const float*)d_in[7];
        Wout = (const float*)d_in[8];
        for (int d = 0; d < 4; d++) {
            dtb[d]  = (const float*)d_in[9 + 3 * d + 0];
            alog[d] = (const float*)d_in[9 + 3 * d + 1];
            Dp[d]   = (const float*)d_in[9 + 3 * d + 2];
        }
        v2h = (const int*)d_in[21];
    } else {
        xH = (const float*)d_in[0];  xV = (const float*)d_in[1];
        WinH = (const float*)d_in[2]; WinV = (const float*)d_in[3];
        for (int d = 0; d < 4; d++) {
            dtb[d]  = (const float*)d_in[4 + d];
            alog[d] = (const float*)d_in[8 + d];
            Dp[d]   = (const float*)d_in[12 + d];
        }
        WoHF = (const float*)d_in[16]; WoHB = (const float*)d_in[17];
        WoVF = (const float*)d_in[18]; WoVB = (const float*)d_in[19];
        Wout = (const float*)d_in[20];
        v2h = (const int*)d_in[21];
    }

    SP sp;
    for (int d = 0; d < 4; d++) { sp.alog[d] = alog[d]; sp.Dp[d] = Dp[d]; }

    cudaFuncSetAttribute(gemm_mma<0>, cudaFuncAttributeMaxDynamicSharedMemorySize, GSMEM);
    cudaFuncSetAttribute(gemm_mma<1>, cudaFuncAttributeMaxDynamicSharedMemorySize, GSMEM);
    cudaFuncSetAttribute(gemm_mma<2>, cudaFuncAttributeMaxDynamicSharedMemorySize, GSMEM);

    // launches 0-2: prep; launch 3 = gemm<0> (profiler lands on our index 3)
    conv_all<<<dim3((int)(AXSZ / 4 / 256), 2), 256>>>(xH, xV);
    wsplit_in<<<2 * 1152, 256>>>(WinH, WinV);
    wsplit_rest<<<2048, 256>>>(WoHF, WoHB, WoVF, WoVB, Wout);

    gemm_mma<0><<<dim3(9, MM / 128, 2), 256, GSMEM>>>(
        nullptr, dtb[0], dtb[1], dtb[2], dtb[3], nullptr);

    // chunked selective scan
    scan_pass1<<<dim3(NCHUNK, BB * NHH, 4), 64>>>(sp);
    scan_pass2<<<NUNIT, 512>>>();
    scan_pass3<<<dim3(NCHUNK, BB * NHH, 4), 64>>>(sp);

    // out-projections (all 4 dirs batched via z): silu + v2h scatter -> cat hi/lo
    gemm_mma<1><<<dim3(2, MM / 128, 4), 256, GSMEM>>>(
        nullptr, nullptr, nullptr, nullptr, nullptr, v2h);

    // final projection
    gemm_mma<2><<<dim3(2, MM / 128, 1), 256, GSMEM>>>(
        (float*)d_out, nullptr, nullptr, nullptr, nullptr, nullptr);
}